// round 4
// baseline (speedup 1.0000x reference)
#include <cuda_runtime.h>
#include <cstdint>

#define BB 512
#define SS 64
#define DD 256
#define NN 100000
#define NM1 99999
#define D2 512

// ---- scratch (device globals: no allocation allowed) ----
__device__ float g_avlast[BB * D2];              // [512, 512] concat(fs_in,fs_out) at last row
__device__ float g_h[BB * D2];                   // [512, 512] relu(av @ W1)
__device__ float g_lasth[BB * DD];               // [512, 256] h @ W2
__device__ float g_lse[BB];                      // per-row logsumexp
__device__ float g_logits_fb[BB * NM1];          // fallback logits buffer (only if out lacks logits)

// ============================================================================
// K0: session length -> last id -> gather + dual adjacency row-aggregation
//     av_last[b, 0:256]   = sum_k adj_in [b,last,k] * emb[item[b,k], :]
//     av_last[b, 256:512] = sum_k adj_out[b,last,k] * emb[item[b,k], :]
// ============================================================================
__global__ void k_avlast(const float* __restrict__ emb,
                         const float* __restrict__ adj_in,
                         const float* __restrict__ adj_out,
                         const float* __restrict__ mask,
                         const int* __restrict__ item,
                         const int* __restrict__ alias_) {
    int b = blockIdx.x, t = threadIdx.x;   // 256 threads
    __shared__ float ain[SS], aout[SS];
    __shared__ int items[SS];
    __shared__ int s_last;
    if (t == 0) {
        float s = 0.f;
        for (int i = 0; i < SS; i++) s += mask[b * SS + i];
        int rm = (int)s;                               // matches astype(int32) truncation
        s_last = alias_[b * SS + rm - 1];
    }
    __syncthreads();
    int last = s_last;
    if (t < SS) {
        ain[t]   = adj_in [((size_t)b * SS + last) * SS + t];   // LAYERS==1: adj**1 == adj
        aout[t]  = adj_out[((size_t)b * SS + last) * SS + t];
        items[t] = item[b * SS + t];
    }
    __syncthreads();
    int d = t;  // 0..255
    float aI = 0.f, aO = 0.f;
#pragma unroll 8
    for (int k = 0; k < SS; k++) {
        float e = emb[(size_t)items[k] * DD + d];
        aI = fmaf(ain[k],  e, aI);
        aO = fmaf(aout[k], e, aO);
    }
    g_avlast[b * D2 + d]      = aI;
    g_avlast[b * D2 + DD + d] = aO;
}

// ============================================================================
// K1/K2: small fp32 GEMM (C = A[M,K] @ B[K,Ncols]), optional relu epilogue
//        64x64 tile, 256 threads, 4x4 micro-tile. M,K,Ncols multiples of 64.
// ============================================================================
__global__ __launch_bounds__(256) void k_gemm(const float* __restrict__ A,
                                              const float* __restrict__ Bm,
                                              float* __restrict__ C,
                                              int M, int K, int Ncols, int relu) {
    __shared__ float As[64][17];
    __shared__ float Bs[16][65];
    int tid = threadIdx.x;
    int ty = tid >> 4, tx = tid & 15;
    int row0 = blockIdx.y * 64, col0 = blockIdx.x * 64;
    float acc[4][4] = {};
    for (int k0 = 0; k0 < K; k0 += 16) {
        for (int i = tid; i < 64 * 16; i += 256) {
            int r = i >> 4, c = i & 15;
            As[r][c] = A[(size_t)(row0 + r) * K + k0 + c];
        }
        for (int i = tid; i < 16 * 64; i += 256) {
            int r = i >> 6, c = i & 63;
            Bs[r][c] = Bm[(size_t)(k0 + r) * Ncols + col0 + c];
        }
        __syncthreads();
#pragma unroll
        for (int kk = 0; kk < 16; kk++) {
            float a[4], bv[4];
#pragma unroll
            for (int i = 0; i < 4; i++) a[i] = As[ty * 4 + i][kk];
#pragma unroll
            for (int j = 0; j < 4; j++) bv[j] = Bs[kk][tx * 4 + j];
#pragma unroll
            for (int i = 0; i < 4; i++)
#pragma unroll
                for (int j = 0; j < 4; j++)
                    acc[i][j] = fmaf(a[i], bv[j], acc[i][j]);
        }
        __syncthreads();
    }
#pragma unroll
    for (int i = 0; i < 4; i++)
#pragma unroll
        for (int j = 0; j < 4; j++) {
            float v = acc[i][j];
            if (relu) v = fmaxf(v, 0.f);
            C[(size_t)(row0 + ty * 4 + i) * Ncols + col0 + tx * 4 + j] = v;
        }
}

// ============================================================================
// K3: logits[512, 99999] = last_h[512,256] @ emb[1:100000].T  (TF32 mma.sync)
//     Block tile 128x128, 8 warps as 4(M) x 2(N), K-chunk 32, pad-4 smem swizzle.
//     Grid (4, 782): blockIdx.x (M) fastest so concurrent blocks share emb tiles in L2.
// ============================================================================
__device__ __forceinline__ uint32_t f2tf(float x) {
    uint32_t r;
    asm("cvt.rna.tf32.f32 %0, %1;" : "=r"(r) : "f"(x));
    return r;
}
__device__ __forceinline__ void mma_tf32(float* c, uint32_t a0, uint32_t a1,
                                         uint32_t a2, uint32_t a3,
                                         uint32_t b0, uint32_t b1) {
    asm volatile("mma.sync.aligned.m16n8k8.row.col.f32.tf32.tf32.f32 "
                 "{%0,%1,%2,%3},{%4,%5,%6,%7},{%8,%9},{%0,%1,%2,%3};"
                 : "+f"(c[0]), "+f"(c[1]), "+f"(c[2]), "+f"(c[3])
                 : "r"(a0), "r"(a1), "r"(a2), "r"(a3), "r"(b0), "r"(b1));
}

__global__ __launch_bounds__(256) void k_logits(const float* __restrict__ Ah,
                                                const float* __restrict__ emb,
                                                float* __restrict__ out) {
    __shared__ uint32_t As[128][36];   // pad 4: (r*36 + k) % 32 pattern -> conflict-free frags
    __shared__ uint32_t Bs[128][36];
    int mt = blockIdx.x * 128;
    int nt = blockIdx.y * 128;
    int t = threadIdx.x;
    int warp = t >> 5, lane = t & 31;
    int wm = warp >> 1, wn = warp & 1;   // warp computes 32(M) x 64(N)
    int g = lane >> 2, tq = lane & 3;

    float c[2][8][4];
#pragma unroll
    for (int mi = 0; mi < 2; mi++)
#pragma unroll
        for (int ni = 0; ni < 8; ni++)
#pragma unroll
            for (int q = 0; q < 4; q++) c[mi][ni][q] = 0.f;

    for (int k0 = 0; k0 < DD; k0 += 32) {
        // A chunk: rows mt..mt+127, k0..k0+31 (always in-bounds: M=512)
#pragma unroll
        for (int i = t; i < 128 * 8; i += 256) {
            int r = i >> 3, cc = (i & 7) << 2;
            float4 v = *(const float4*)(Ah + (size_t)(mt + r) * DD + k0 + cc);
            As[r][cc + 0] = f2tf(v.x); As[r][cc + 1] = f2tf(v.y);
            As[r][cc + 2] = f2tf(v.z); As[r][cc + 3] = f2tf(v.w);
        }
        // B chunk: emb rows nt+1 .. nt+128 (logits col j <-> emb row j+1), guarded
#pragma unroll
        for (int i = t; i < 128 * 8; i += 256) {
            int r = i >> 3, cc = (i & 7) << 2;
            int er = nt + 1 + r;
            float4 v = make_float4(0.f, 0.f, 0.f, 0.f);
            if (er < NN) v = *(const float4*)(emb + (size_t)er * DD + k0 + cc);
            Bs[r][cc + 0] = f2tf(v.x); Bs[r][cc + 1] = f2tf(v.y);
            Bs[r][cc + 2] = f2tf(v.z); Bs[r][cc + 3] = f2tf(v.w);
        }
        __syncthreads();
#pragma unroll
        for (int ks = 0; ks < 32; ks += 8) {
            uint32_t a0[2], a1[2], a2[2], a3[2];
#pragma unroll
            for (int mi = 0; mi < 2; mi++) {
                int r = wm * 32 + mi * 16 + g;
                a0[mi] = As[r][ks + tq];
                a1[mi] = As[r + 8][ks + tq];
                a2[mi] = As[r][ks + 4 + tq];
                a3[mi] = As[r + 8][ks + 4 + tq];
            }
#pragma unroll
            for (int ni = 0; ni < 8; ni++) {
                int nr = wn * 64 + ni * 8 + g;
                uint32_t b0 = Bs[nr][ks + tq];
                uint32_t b1 = Bs[nr][ks + 4 + tq];
                mma_tf32(c[0][ni], a0[0], a1[0], a2[0], a3[0], b0, b1);
                mma_tf32(c[1][ni], a0[1], a1[1], a2[1], a3[1], b0, b1);
            }
        }
        __syncthreads();
    }
    // epilogue: c0->(g,2t) c1->(g,2t+1) c2->(g+8,2t) c3->(g+8,2t+1)
#pragma unroll
    for (int mi = 0; mi < 2; mi++) {
        int r0 = mt + wm * 32 + mi * 16 + g;
#pragma unroll
        for (int ni = 0; ni < 8; ni++) {
            int c0 = nt + wn * 64 + ni * 8 + 2 * tq;
            if (c0 < NM1) {
                out[(size_t)r0 * NM1 + c0]       = c[mi][ni][0];
                out[(size_t)(r0 + 8) * NM1 + c0] = c[mi][ni][2];
            }
            if (c0 + 1 < NM1) {
                out[(size_t)r0 * NM1 + c0 + 1]       = c[mi][ni][1];
                out[(size_t)(r0 + 8) * NM1 + c0 + 1] = c[mi][ni][3];
            }
        }
    }
}

// ============================================================================
// K4: per-row logsumexp (online max; rescale path is rare ~ln(N) times/thread)
// ============================================================================
__global__ void k_lse(const float* __restrict__ logits, float* __restrict__ lse) {
    int b = blockIdx.x, t = threadIdx.x;   // 256 threads
    const float* row = logits + (size_t)b * NM1;
    float m = -3.0e38f, s = 0.f;
    for (int i = t; i < NM1; i += 256) {
        float x = row[i];
        if (x > m) { s = s * __expf(m - x) + 1.f; m = x; }
        else       { s += __expf(x - m); }
    }
    __shared__ float sm[256], ss[256];
    sm[t] = m; ss[t] = s;
    __syncthreads();
    for (int o = 128; o > 0; o >>= 1) {
        if (t < o) {
            float m2 = sm[t + o], s2 = ss[t + o];
            float M = fmaxf(sm[t], m2);
            ss[t] = ss[t] * __expf(sm[t] - M) + s2 * __expf(m2 - M);
            sm[t] = M;
        }
        __syncthreads();
    }
    if (t == 0) lse[b] = sm[0] + logf(ss[0]);
}

// ============================================================================
// K5: loss = -mean_b( logits[b, tar[b]-1] - lse[b] )
// ============================================================================
__global__ void k_loss(const float* __restrict__ logits, const float* __restrict__ lse,
                       const int* __restrict__ tar, float* __restrict__ loss_out) {
    __shared__ float red[512];
    int t = threadIdx.x;
    int tg = tar[t] - 1;
    red[t] = logits[(size_t)t * NM1 + tg] - lse[t];
    __syncthreads();
    for (int o = 256; o > 0; o >>= 1) {
        if (t < o) red[t] += red[t + o];
        __syncthreads();
    }
    if (t == 0) loss_out[0] = -red[0] / (float)BB;
}

// ============================================================================
// launch
// ============================================================================
extern "C" void kernel_launch(void* const* d_in, const int* in_sizes, int n_in,
                              void* d_out, int out_size) {
    const float* emb    = (const float*)d_in[0];
    const float* W1     = (const float*)d_in[1];
    const float* W2     = (const float*)d_in[2];
    const float* adjI   = (const float*)d_in[3];
    const float* adjO   = (const float*)d_in[4];
    const float* mask   = (const float*)d_in[5];
    const int*   item   = (const int*)d_in[6];
    const int*   alias_ = (const int*)d_in[7];
    const int*   tar    = (const int*)d_in[8];
    float* out = (float*)d_out;

    float *p_av, *p_h, *p_lh, *p_lse, *p_fb;
    cudaGetSymbolAddress((void**)&p_av,  g_avlast);
    cudaGetSymbolAddress((void**)&p_h,   g_h);
    cudaGetSymbolAddress((void**)&p_lh,  g_lasth);
    cudaGetSymbolAddress((void**)&p_lse, g_lse);
    cudaGetSymbolAddress((void**)&p_fb,  g_logits_fb);

    const long long NL = (long long)BB * NM1;
    float *loss_ptr, *logits_ptr;
    if ((long long)out_size >= NL + 1)      { loss_ptr = out;  logits_ptr = out + 1; }  // (loss, logits)
    else if ((long long)out_size == NL)     { loss_ptr = p_fb; logits_ptr = out; }      // logits only
    else                                    { loss_ptr = out;  logits_ptr = p_fb; }     // loss only

    k_avlast<<<BB, 256>>>(emb, adjI, adjO, mask, item, alias_);
    k_gemm<<<dim3(D2 / 64, BB / 64), 256>>>(p_av, W1, p_h,  BB, D2, D2, 1);  // relu(av@W1)
    k_gemm<<<dim3(DD / 64, BB / 64), 256>>>(p_h,  W2, p_lh, BB, D2, DD, 0);  // h@W2
    k_logits<<<dim3(4, (NM1 + 127) / 128), 256>>>(p_lh, emb, logits_ptr);
    k_lse<<<BB, 256>>>(logits_ptr, p_lse);
    k_loss<<<1, 512>>>(logits_ptr, p_lse, tar, loss_ptr);
}

// round 5
// speedup vs baseline: 1.2871x; 1.2871x over previous
#include <cuda_runtime.h>
#include <cstdint>

#define BB 512
#define SS 64
#define DD 256
#define NN 100000
#define NM1 99999
#define D2 512
#define NBLK 782            // ceil(99999/128)

// ---- scratch (device globals: no allocation allowed) ----
__device__ float g_avlast[BB * D2];
__device__ float g_h[BB * D2];
__device__ float g_lasth[BB * DD];
__device__ float g_lse[BB];
__device__ float g_pmax[BB * NBLK];
__device__ float g_psum[BB * NBLK];
__device__ float g_logits_fb[BB * NM1];

// ============================================================================
// K0: session length -> last id -> gather + dual adjacency row-aggregation
// ============================================================================
__global__ void k_avlast(const float* __restrict__ emb,
                         const float* __restrict__ adj_in,
                         const float* __restrict__ adj_out,
                         const float* __restrict__ mask,
                         const int* __restrict__ item,
                         const int* __restrict__ alias_) {
    int b = blockIdx.x, t = threadIdx.x;   // 256 threads
    __shared__ float ain[SS], aout[SS];
    __shared__ int items[SS];
    __shared__ int s_last;
    if (t == 0) {
        float s = 0.f;
        for (int i = 0; i < SS; i++) s += mask[b * SS + i];
        int rm = (int)s;
        s_last = alias_[b * SS + rm - 1];
    }
    __syncthreads();
    int last = s_last;
    if (t < SS) {
        ain[t]   = adj_in [((size_t)b * SS + last) * SS + t];
        aout[t]  = adj_out[((size_t)b * SS + last) * SS + t];
        items[t] = item[b * SS + t];
    }
    __syncthreads();
    int d = t;
    float aI = 0.f, aO = 0.f;
#pragma unroll 8
    for (int k = 0; k < SS; k++) {
        float e = emb[(size_t)items[k] * DD + d];
        aI = fmaf(ain[k],  e, aI);
        aO = fmaf(aout[k], e, aO);
    }
    g_avlast[b * D2 + d]      = aI;
    g_avlast[b * D2 + DD + d] = aO;
}

__device__ __forceinline__ uint32_t f2tf(float x) {
    uint32_t r;
    asm("cvt.rna.tf32.f32 %0, %1;" : "=r"(r) : "f"(x));
    return r;
}

// ============================================================================
// K1/K2: small fp32 GEMM, 32(M)x64(N) tile, 256 threads, 2x4 micro-tile.
//        mode: 1 = relu epilogue, 2 = round output to tf32 (for MMA consumer)
// ============================================================================
__global__ __launch_bounds__(256) void k_gemm(const float* __restrict__ A,
                                              const float* __restrict__ Bm,
                                              float* __restrict__ C,
                                              int M, int K, int Ncols, int mode) {
    __shared__ float As[32][17];
    __shared__ float Bs[16][65];
    int t = threadIdx.x;
    int tx = t & 15, ty = t >> 4;
    int row0 = blockIdx.y * 32, col0 = blockIdx.x * 64;
    float acc[2][4] = {};
    for (int k0 = 0; k0 < K; k0 += 16) {
        for (int i = t; i < 32 * 16; i += 256) {
            int r = i >> 4, c = i & 15;
            As[r][c] = A[(size_t)(row0 + r) * K + k0 + c];
        }
        for (int i = t; i < 16 * 64; i += 256) {
            int r = i >> 6, c = i & 63;
            Bs[r][c] = Bm[(size_t)(k0 + r) * Ncols + col0 + c];
        }
        __syncthreads();
#pragma unroll
        for (int kk = 0; kk < 16; kk++) {
            float a0 = As[ty * 2][kk], a1 = As[ty * 2 + 1][kk];
            float bv[4];
#pragma unroll
            for (int j = 0; j < 4; j++) bv[j] = Bs[kk][tx * 4 + j];
#pragma unroll
            for (int j = 0; j < 4; j++) {
                acc[0][j] = fmaf(a0, bv[j], acc[0][j]);
                acc[1][j] = fmaf(a1, bv[j], acc[1][j]);
            }
        }
        __syncthreads();
    }
#pragma unroll
    for (int i = 0; i < 2; i++)
#pragma unroll
        for (int j = 0; j < 4; j++) {
            float v = acc[i][j];
            if (mode == 1) v = fmaxf(v, 0.f);
            if (mode == 2) v = __uint_as_float(f2tf(v));
            C[(size_t)(row0 + ty * 2 + i) * Ncols + col0 + tx * 4 + j] = v;
        }
}

// ============================================================================
// K3: logits[512,99999] = last_h[512,256] @ emb[1:].T  (TF32 mma.sync)
//     128x128 tile, 8 warps (4M x 2N), K-chunk 32, cp.async 2-stage pipeline,
//     ldmatrix.x4 fragment loads, fused per-row (max, sumexp) partials.
//     A pre-rounded to tf32 by producer; B raw fp32 (HW truncates mantissa).
// ============================================================================
__device__ __forceinline__ void mma_tf32(float* c, uint32_t a0, uint32_t a1,
                                         uint32_t a2, uint32_t a3,
                                         uint32_t b0, uint32_t b1) {
    asm volatile("mma.sync.aligned.m16n8k8.row.col.f32.tf32.tf32.f32 "
                 "{%0,%1,%2,%3},{%4,%5,%6,%7},{%8,%9},{%0,%1,%2,%3};"
                 : "+f"(c[0]), "+f"(c[1]), "+f"(c[2]), "+f"(c[3])
                 : "r"(a0), "r"(a1), "r"(a2), "r"(a3), "r"(b0), "r"(b1));
}

#define PITCH 36                       // words per smem row (144B, conflict-free LDSM)
#define STG_W (128 * PITCH)            // words per stage matrix
#define SMEM_LOGITS_BYTES (4 * STG_W * 4)

__device__ __forceinline__ void stage_logits(uint32_t sA, uint32_t sB,
                                             const float* __restrict__ Ah,
                                             const float* __restrict__ emb,
                                             int mt, int nt, int k0, int t) {
#pragma unroll
    for (int u0 = 0; u0 < 4; u0++) {
        int u = t + u0 * 256;
        int r = u >> 3, c = (u & 7) << 2;       // c in floats (16B chunks)
        uint32_t da = sA + (uint32_t)(r * PITCH + c) * 4;
        const float* srcA = Ah + (size_t)(mt + r) * DD + k0 + c;
        asm volatile("cp.async.cg.shared.global [%0], [%1], 16;\n"
                     :: "r"(da), "l"(srcA));
        int er = nt + 1 + r;
        uint32_t db = sB + (uint32_t)(r * PITCH + c) * 4;
        const float* srcB = emb + (size_t)(er < NN ? er : 0) * DD + k0 + c;
        int sz = (er < NN) ? 16 : 0;
        asm volatile("cp.async.cg.shared.global [%0], [%1], 16, %2;\n"
                     :: "r"(db), "l"(srcB), "r"(sz));
    }
}

__global__ __launch_bounds__(256) void k_logits(const float* __restrict__ Ah,
                                                const float* __restrict__ emb,
                                                float* __restrict__ out) {
    extern __shared__ float smem[];
    uint32_t sbase = (uint32_t)__cvta_generic_to_shared(smem);
    const uint32_t ASZ = STG_W * 4;   // bytes per stage matrix
    uint32_t sA[2] = { sbase,           sbase + ASZ };
    uint32_t sB[2] = { sbase + 2 * ASZ, sbase + 3 * ASZ };

    int mt = blockIdx.x * 128;
    int nt = blockIdx.y * 128;
    int t = threadIdx.x;
    int warp = t >> 5, lane = t & 31;
    int wm = warp >> 1, wn = warp & 1;
    int g = lane >> 2, tq = lane & 3;
    // ldmatrix lane addressing: block b = lane>>3
    int lr = lane & 7, bb = lane >> 3;
    int rowadd = lr + ((bb & 1) << 3);
    int coladd = (bb >> 1) << 2;

    float c[2][8][4];
#pragma unroll
    for (int mi = 0; mi < 2; mi++)
#pragma unroll
        for (int ni = 0; ni < 8; ni++)
#pragma unroll
            for (int q = 0; q < 4; q++) c[mi][ni][q] = 0.f;

    stage_logits(sA[0], sB[0], Ah, emb, mt, nt, 0, t);
    asm volatile("cp.async.commit_group;");

    for (int s = 0; s < 8; s++) {
        if (s < 7) stage_logits(sA[(s + 1) & 1], sB[(s + 1) & 1], Ah, emb, mt, nt, (s + 1) * 32, t);
        asm volatile("cp.async.commit_group;");
        asm volatile("cp.async.wait_group 1;");
        __syncthreads();
        uint32_t cA = sA[s & 1], cB = sB[s & 1];
#pragma unroll
        for (int ks = 0; ks < 32; ks += 8) {
            uint32_t a[2][4];
#pragma unroll
            for (int mi = 0; mi < 2; mi++) {
                uint32_t addr = cA + (uint32_t)((wm * 32 + mi * 16 + rowadd) * PITCH + ks + coladd) * 4;
                asm volatile("ldmatrix.sync.aligned.m8n8.x4.shared.b16 {%0,%1,%2,%3}, [%4];"
                             : "=r"(a[mi][0]), "=r"(a[mi][1]), "=r"(a[mi][2]), "=r"(a[mi][3])
                             : "r"(addr));
            }
#pragma unroll
            for (int np = 0; np < 4; np++) {
                uint32_t b0, b1, b2, b3;
                uint32_t addr = cB + (uint32_t)((wn * 64 + np * 16 + rowadd) * PITCH + ks + coladd) * 4;
                asm volatile("ldmatrix.sync.aligned.m8n8.x4.shared.b16 {%0,%1,%2,%3}, [%4];"
                             : "=r"(b0), "=r"(b1), "=r"(b2), "=r"(b3)
                             : "r"(addr));
#pragma unroll
                for (int mi = 0; mi < 2; mi++) {
                    mma_tf32(c[mi][2 * np],     a[mi][0], a[mi][1], a[mi][2], a[mi][3], b0, b2);
                    mma_tf32(c[mi][2 * np + 1], a[mi][0], a[mi][1], a[mi][2], a[mi][3], b1, b3);
                }
            }
        }
        __syncthreads();
    }

    // ---- logits stores (c0/c1 -> row r0; c2/c3 -> row r0+8) ----
#pragma unroll
    for (int mi = 0; mi < 2; mi++) {
        int r0 = mt + wm * 32 + mi * 16 + g;
#pragma unroll
        for (int ni = 0; ni < 8; ni++) {
            int c0 = nt + wn * 64 + ni * 8 + 2 * tq;
            if (c0 < NM1) {
                out[(size_t)r0 * NM1 + c0]       = c[mi][ni][0];
                out[(size_t)(r0 + 8) * NM1 + c0] = c[mi][ni][2];
            }
            if (c0 + 1 < NM1) {
                out[(size_t)r0 * NM1 + c0 + 1]       = c[mi][ni][1];
                out[(size_t)(r0 + 8) * NM1 + c0 + 1] = c[mi][ni][3];
            }
        }
    }

    // ---- fused LSE partials: per-row (max, sumexp over this block's 128 cols) ----
    float* redM = smem;         // reuse stage buffers (post-sync)
    float* redS = smem + 256;
#pragma unroll
    for (int slot = 0; slot < 4; slot++) {
        int mi = slot >> 1, h = slot & 1;    // h: 0 -> q{0,1} (row +0), 1 -> q{2,3} (row +8)
        float m = -3.0e38f;
#pragma unroll
        for (int ni = 0; ni < 8; ni++) {
            int cbase = nt + wn * 64 + ni * 8 + 2 * tq;
            float v0 = (cbase     < NM1) ? c[mi][ni][2 * h]     : -3.0e38f;
            float v1 = (cbase + 1 < NM1) ? c[mi][ni][2 * h + 1] : -3.0e38f;
            m = fmaxf(m, fmaxf(v0, v1));
        }
        float sum = 0.f;
#pragma unroll
        for (int ni = 0; ni < 8; ni++) {
            int cbase = nt + wn * 64 + ni * 8 + 2 * tq;
            float v0 = (cbase     < NM1) ? c[mi][ni][2 * h]     : -3.0e38f;
            float v1 = (cbase + 1 < NM1) ? c[mi][ni][2 * h + 1] : -3.0e38f;
            sum += __expf(v0 - m) + __expf(v1 - m);
        }
#pragma unroll
        for (int off = 1; off <= 2; off <<= 1) {
            float m2 = __shfl_xor_sync(0xffffffffu, m, off);
            float s2 = __shfl_xor_sync(0xffffffffu, sum, off);
            float M = fmaxf(m, m2);
            sum = sum * __expf(m - M) + s2 * __expf(m2 - M);
            m = M;
        }
        if (tq == 0) {
            redM[(warp * 4 + slot) * 8 + g] = m;
            redS[(warp * 4 + slot) * 8 + g] = sum;
        }
    }
    __syncthreads();
    if (t < 128) {
        int wmr = t >> 5, slot = (t >> 3) & 3, gg = t & 7;
        int i1 = ((wmr * 2)     * 4 + slot) * 8 + gg;
        int i2 = ((wmr * 2 + 1) * 4 + slot) * 8 + gg;
        float m1 = redM[i1], s1 = redS[i1];
        float m2 = redM[i2], s2 = redS[i2];
        float M = fmaxf(m1, m2);
        float S = s1 * __expf(m1 - M) + s2 * __expf(m2 - M);
        int row = mt + wmr * 32 + (slot >> 1) * 16 + (slot & 1) * 8 + gg;
        g_pmax[(size_t)row * NBLK + blockIdx.y] = M;
        g_psum[(size_t)row * NBLK + blockIdx.y] = S;
    }
}

// ============================================================================
// K4: finalize LSE from per-block partials
// ============================================================================
__global__ void k_lsefin(float* __restrict__ lse) {
    int b = blockIdx.x, t = threadIdx.x;   // 256 threads
    float m = -3.0e38f, s = 0.f;
    for (int i = t; i < NBLK; i += 256) {
        float m2 = g_pmax[(size_t)b * NBLK + i];
        float s2 = g_psum[(size_t)b * NBLK + i];
        float M = fmaxf(m, m2);
        s = s * __expf(m - M) + s2 * __expf(m2 - M);
        m = M;
    }
    __shared__ float sm[256], ss[256];
    sm[t] = m; ss[t] = s;
    __syncthreads();
    for (int o = 128; o > 0; o >>= 1) {
        if (t < o) {
            float m2 = sm[t + o], s2 = ss[t + o];
            float M = fmaxf(sm[t], m2);
            ss[t] = ss[t] * __expf(sm[t] - M) + s2 * __expf(m2 - M);
            sm[t] = M;
        }
        __syncthreads();
    }
    if (t == 0) lse[b] = sm[0] + logf(ss[0]);
}

// ============================================================================
// K5: loss = -mean_b( logits[b, tar[b]-1] - lse[b] )
// ============================================================================
__global__ void k_loss(const float* __restrict__ logits, const float* __restrict__ lse,
                       const int* __restrict__ tar, float* __restrict__ loss_out) {
    __shared__ float red[512];
    int t = threadIdx.x;
    int tg = tar[t] - 1;
    red[t] = logits[(size_t)t * NM1 + tg] - lse[t];
    __syncthreads();
    for (int o = 256; o > 0; o >>= 1) {
        if (t < o) red[t] += red[t + o];
        __syncthreads();
    }
    if (t == 0) loss_out[0] = -red[0] / (float)BB;
}

// ============================================================================
// launch
// ============================================================================
extern "C" void kernel_launch(void* const* d_in, const int* in_sizes, int n_in,
                              void* d_out, int out_size) {
    const float* emb    = (const float*)d_in[0];
    const float* W1     = (const float*)d_in[1];
    const float* W2     = (const float*)d_in[2];
    const float* adjI   = (const float*)d_in[3];
    const float* adjO   = (const float*)d_in[4];
    const float* mask   = (const float*)d_in[5];
    const int*   item   = (const int*)d_in[6];
    const int*   alias_ = (const int*)d_in[7];
    const int*   tar    = (const int*)d_in[8];
    float* out = (float*)d_out;

    float *p_av, *p_h, *p_lh, *p_lse, *p_fb;
    cudaGetSymbolAddress((void**)&p_av,  g_avlast);
    cudaGetSymbolAddress((void**)&p_h,   g_h);
    cudaGetSymbolAddress((void**)&p_lh,  g_lasth);
    cudaGetSymbolAddress((void**)&p_lse, g_lse);
    cudaGetSymbolAddress((void**)&p_fb,  g_logits_fb);

    static int smem_set = 0;
    if (!smem_set) {
        cudaFuncSetAttribute(k_logits, cudaFuncAttributeMaxDynamicSharedMemorySize,
                             SMEM_LOGITS_BYTES);
        smem_set = 1;
    }

    const long long NL = (long long)BB * NM1;
    float *loss_ptr, *logits_ptr;
    if ((long long)out_size >= NL + 1)      { loss_ptr = out;  logits_ptr = out + 1; }
    else if ((long long)out_size == NL)     { loss_ptr = p_fb; logits_ptr = out; }
    else                                    { loss_ptr = out;  logits_ptr = p_fb; }

    k_avlast<<<BB, 256>>>(emb, adjI, adjO, mask, item, alias_);
    k_gemm<<<dim3(D2 / 64, BB / 32), 256>>>(p_av, W1, p_h,  BB, D2, D2, 1);  // relu(av@W1)
    k_gemm<<<dim3(DD / 64, BB / 32), 256>>>(p_h,  W2, p_lh, BB, D2, DD, 2);  // (h@W2) -> tf32
    k_logits<<<dim3(4, NBLK), 256, SMEM_LOGITS_BYTES>>>(p_lh, emb, logits_ptr);
    k_lsefin<<<BB, 256>>>(p_lse);
    k_loss<<<1, 512>>>(logits_ptr, p_lse, tar, loss_ptr);
}